// round 6
// baseline (speedup 1.0000x reference)
#include <cuda_runtime.h>
#include <math.h>

// Problem constants (fixed by the reference)
#define BATCH   2
#define SEQ     2048
#define DMODEL  1024
#define NHEADS  16
#define HDIM    64
#define ROWS    (BATCH * SEQ)        // 4096
#define QKVCOLS (3 * DMODEL)         // 3072

// Scratch (static device globals — allocation-free per harness rules)
__device__ float    g_qkv[(size_t)ROWS * QKVCOLS];      // 50 MB
__device__ float    g_att[(size_t)ROWS * DMODEL];       // 16 MB
__device__ unsigned g_wqkvT[(size_t)QKVCOLS * DMODEL];  // 12.6 MB (tf32 bits)
__device__ unsigned g_wprojT[(size_t)DMODEL * DMODEL];  // 4.2 MB  (tf32 bits)

// ---------------------------------------------------------------------------
// Helpers
// ---------------------------------------------------------------------------
__device__ __forceinline__ unsigned f2tf32(float x) {
    unsigned r;
    asm("cvt.rna.tf32.f32 %0, %1;" : "=r"(r) : "f"(x));
    return r;
}

// D += A(16x8) * B(8x8), tf32 inputs, fp32 accumulate
#define MMA_TF32(d, a, b)                                                     \
    asm volatile(                                                             \
        "mma.sync.aligned.m16n8k8.row.col.f32.tf32.tf32.f32 "                 \
        "{%0,%1,%2,%3},{%4,%5,%6,%7},{%8,%9},{%0,%1,%2,%3};"                  \
        : "+f"((d)[0]), "+f"((d)[1]), "+f"((d)[2]), "+f"((d)[3])              \
        : "r"((a)[0]), "r"((a)[1]), "r"((a)[2]), "r"((a)[3]),                 \
          "r"((b)[0]), "r"((b)[1]))

#define LDMATRIX_X4(r0, r1, r2, r3, addr)                                     \
    asm volatile(                                                             \
        "ldmatrix.sync.aligned.m8n8.x4.shared.b16 {%0,%1,%2,%3}, [%4];"       \
        : "=r"(r0), "=r"(r1), "=r"(r2), "=r"(r3) : "r"(addr))

__device__ __forceinline__ unsigned smem_u32(const void* p) {
    return (unsigned)__cvta_generic_to_shared(p);
}

// ---------------------------------------------------------------------------
// Weight pre-transpose: W[K][N] (f32) -> Wt[N][K] (tf32 bits)
// ---------------------------------------------------------------------------
__global__ void transpose_tf32_kernel(const float* __restrict__ W,
                                      unsigned* __restrict__ Wt,
                                      int K, int N)
{
    __shared__ unsigned t[32][33];
    const int x = blockIdx.x * 32 + threadIdx.x;   // n
    const int y = blockIdx.y * 32;                 // k base
#pragma unroll
    for (int j = threadIdx.y; j < 32; j += 8)
        t[j][threadIdx.x] = f2tf32(W[(size_t)(y + j) * N + x]);
    __syncthreads();
    const int xo = blockIdx.y * 32 + threadIdx.x;  // k
    const int yo = blockIdx.x * 32;                // n base
#pragma unroll
    for (int j = threadIdx.y; j < 32; j += 8)
        Wt[(size_t)(yo + j) * K + xo] = t[threadIdx.x][j];
}

// ---------------------------------------------------------------------------
// TF32 tensor-core GEMM: C[M,N] = A[M,K] @ W[K,N] + bias[N], with W given
// pre-transposed as Wt[N][K] in tf32 bits.
// Block 128x128, BK=32, 256 threads (8 warps, warp tile 32x64).
// Smem: As[2][128][36] (m-major tf32), Bs[2][128][36] (n-major tf32).
// All fragments via ldmatrix.x4 (conflict-free; 24 LDSM + 64 MMA /warp/tile).
// ---------------------------------------------------------------------------
#define GEMM_BUF   (128 * 36)
#define GEMM_SMEM_BYTES (4 * GEMM_BUF * 4)

__global__ __launch_bounds__(256, 2)
void gemm_tf32_kernel(const float* __restrict__ A,
                      const unsigned* __restrict__ Wt,
                      const float* __restrict__ bias,
                      float* __restrict__ C,
                      int M, int N, int K)
{
    extern __shared__ unsigned gsm[];
    unsigned* As = gsm;                  // [2][128][36]
    unsigned* Bs = gsm + 2 * GEMM_BUF;   // [2][128][36]

    const int tid  = threadIdx.x;
    const int lane = tid & 31;
    const int warp = tid >> 5;
    const int wm   = (warp >> 1) * 32;   // warp row offset in block tile
    const int wn   = (warp & 1) * 64;    // warp col offset
    const int row0 = blockIdx.y * 128;
    const int col0 = blockIdx.x * 128;

    float acc[2][8][4];
#pragma unroll
    for (int mt = 0; mt < 2; mt++)
#pragma unroll
        for (int nt = 0; nt < 8; nt++)
#pragma unroll
            for (int c = 0; c < 4; c++) acc[mt][nt][c] = 0.0f;

    // Loader coordinates: both tiles are 128 rows x 32 cols (float4/uint4)
    const int lr = tid >> 3;             // 0..31 (+32p)
    const int lc = (tid & 7) * 4;        // k-col
    const float*    Ap = A  + (size_t)(row0 + lr) * K + lc;
    const unsigned* Bp = Wt + (size_t)(col0 + lr) * K + lc;

    // ldmatrix per-lane base addresses
    const unsigned aRow = (lane & 15);
    const unsigned aCol = (lane >> 4) * 4;
    const unsigned a_ldm = smem_u32(As) + ((wm + aRow) * 36 + aCol) * 4;
    const unsigned bRow = (lane & 7) + ((lane & 16) >> 1);
    const unsigned bCol = (lane & 8) ? 4u : 0u;
    const unsigned b_ldm = smem_u32(Bs) + ((wn + bRow) * 36 + bCol) * 4;

    // Load first K-tile into buffer 0
    {
#pragma unroll
        for (int p = 0; p < 4; p++) {
            float4 av = *(const float4*)(Ap + (size_t)(p * 32) * K);
            uint4 u;
            u.x = f2tf32(av.x); u.y = f2tf32(av.y);
            u.z = f2tf32(av.z); u.w = f2tf32(av.w);
            *(uint4*)&As[(lr + p * 32) * 36 + lc] = u;
            *(uint4*)&Bs[(lr + p * 32) * 36 + lc] =
                *(const uint4*)(Bp + (size_t)(p * 32) * K);
        }
    }
    __syncthreads();

    int cur = 0;
    for (int k0 = 0; k0 < K; k0 += 32) {
        const int k1 = k0 + 32;
        float4 stA[4];
        uint4  stB[4];
        if (k1 < K) {
#pragma unroll
            for (int p = 0; p < 4; p++) {
                stA[p] = *(const float4*)(Ap + k1 + (size_t)(p * 32) * K);
                stB[p] = *(const uint4*)(Bp + k1 + (size_t)(p * 32) * K);
            }
        }

        const unsigned aBuf = a_ldm + cur * GEMM_BUF * 4;
        const unsigned bBuf = b_ldm + cur * GEMM_BUF * 4;
#pragma unroll
        for (int ks = 0; ks < 4; ks++) {
            const int k8 = ks * 8;
            unsigned af[2][4];
#pragma unroll
            for (int mt = 0; mt < 2; mt++)
                LDMATRIX_X4(af[mt][0], af[mt][1], af[mt][2], af[mt][3],
                            aBuf + (mt * 16 * 36 + k8) * 4);
            unsigned bf[8][2];
#pragma unroll
            for (int ntp = 0; ntp < 4; ntp++)
                LDMATRIX_X4(bf[2 * ntp][0], bf[2 * ntp][1],
                            bf[2 * ntp + 1][0], bf[2 * ntp + 1][1],
                            bBuf + (ntp * 16 * 36 + k8) * 4);
#pragma unroll
            for (int mt = 0; mt < 2; mt++)
#pragma unroll
                for (int nt = 0; nt < 8; nt++)
                    MMA_TF32(acc[mt][nt], af[mt], bf[nt]);
        }

        if (k1 < K) {
            unsigned* An = As + (cur ^ 1) * GEMM_BUF;
            unsigned* Bn = Bs + (cur ^ 1) * GEMM_BUF;
#pragma unroll
            for (int p = 0; p < 4; p++) {
                uint4 u;
                u.x = f2tf32(stA[p].x); u.y = f2tf32(stA[p].y);
                u.z = f2tf32(stA[p].z); u.w = f2tf32(stA[p].w);
                *(uint4*)&An[(lr + p * 32) * 36 + lc] = u;
                *(uint4*)&Bn[(lr + p * 32) * 36 + lc] = stB[p];
            }
        }
        __syncthreads();
        cur ^= 1;
    }

    // Epilogue: bias + float2 stores
    const int g  = lane >> 2;
    const int t4 = lane & 3;
#pragma unroll
    for (int mt = 0; mt < 2; mt++) {
        const int rA = row0 + wm + mt * 16 + g;
#pragma unroll
        for (int nt = 0; nt < 8; nt++) {
            const int c = col0 + wn + nt * 8 + 2 * t4;
            const float2 bv = *(const float2*)&bias[c];
            float2 o0, o1;
            o0.x = acc[mt][nt][0] + bv.x;
            o0.y = acc[mt][nt][1] + bv.y;
            o1.x = acc[mt][nt][2] + bv.x;
            o1.y = acc[mt][nt][3] + bv.y;
            *(float2*)&C[(size_t)rA * N + c] = o0;
            *(float2*)&C[(size_t)(rA + 8) * N + c] = o1;
        }
    }
}

// ---------------------------------------------------------------------------
// Flash attention v2-style: BQ=128 q-rows/block, BK=64 keys/tile, 8 warps.
// Warp w owns rows [16w,16w+16); softmax in registers; Q persistent in regs;
// ldmatrix for QK B-frags (sK n-major), Q and P A-frags (sP m-major).
//   sK[64][68] tf32, sV[64][72] tf32 (k-major, scalar b-frags), sP[128][68]
// ---------------------------------------------------------------------------
#define SMEM_ATT_BYTES ((64 * 68 + 64 * 72 + 128 * 68) * 4)

__global__ __launch_bounds__(256)
void flash_attn_tf32_kernel(const float* __restrict__ qkv,
                            float* __restrict__ att)
{
    extern __shared__ unsigned asm_[];
    unsigned* sK = asm_;                 // [64][68]
    unsigned* sV = sK + 64 * 68;         // [64][72]
    unsigned* sP = sV + 64 * 72;         // [128][68]  (Q staging, then P)

    const int tid  = threadIdx.x;
    const int lane = tid & 31;
    const int warp = tid >> 5;           // 0..7 -> rows [16w,16w+16)
    const int g    = lane >> 2;          // 0..7
    const int t4   = lane & 3;           // 0..3
    const int wr   = warp * 16;          // warp row base in q-tile

    const int bh = blockIdx.y;
    const int b  = bh / NHEADS;
    const int h  = bh % NHEADS;
    const int qt = gridDim.x - 1 - blockIdx.x;   // heavy tiles first
    const int q0 = qt * 128;

    const size_t rowbase = (size_t)b * SEQ;
    const int qcol = h * HDIM;
    const int kcol = DMODEL + h * HDIM;
    const int vcol = 2 * DMODEL + h * HDIM;

    // ldmatrix base addresses
    const unsigned kRow = (lane & 7) + ((lane & 16) >> 1);
    const unsigned kColOff = (lane & 8) ? 4u : 0u;
    const unsigned k_ldm = smem_u32(sK) + (kRow * 68 + kColOff) * 4;
    const unsigned pRow = wr + (lane & 15);
    const unsigned pColOff = (lane >> 4) * 4;
    const unsigned p_ldm = smem_u32(sP) + (pRow * 68 + pColOff) * 4;

    // ---- Stage Q tile (coalesced) into sP, convert tf32 ----
    for (int i = tid; i < 128 * 16; i += 256) {
        const int r  = i >> 4;
        const int c4 = (i & 15) * 4;
        float4 v = *(const float4*)&qkv[(rowbase + q0 + r) * QKVCOLS + qcol + c4];
        unsigned* d = &sP[r * 68 + c4];
        d[0] = f2tf32(v.x); d[1] = f2tf32(v.y);
        d[2] = f2tf32(v.z); d[3] = f2tf32(v.w);
    }
    __syncthreads();

    // Q a-frags via ldmatrix: qf[ks] covers k-cols [8ks,8ks+8)
    unsigned qf[8][4];
#pragma unroll
    for (int ks = 0; ks < 8; ks++)
        LDMATRIX_X4(qf[ks][0], qf[ks][1], qf[ks][2], qf[ks][3],
                    p_ldm + ks * 8 * 4);

    // Row stats (rows wr+g and wr+g+8) and output accum
    float m0 = -1e30f, m1 = -1e30f, l0 = 0.0f, l1 = 0.0f;
    float o[8][4];
#pragma unroll
    for (int nt = 0; nt < 8; nt++)
#pragma unroll
        for (int c = 0; c < 4; c++) o[nt][c] = 0.0f;

    const int n_kt = 2 * qt + 2;
    for (int kt = 0; kt < n_kt; kt++) {
        const int k0 = kt * 64;
        // ---- Load K, V tiles (tf32) ----
        for (int i = tid; i < 64 * 16; i += 256) {
            const int r  = i >> 4;
            const int c4 = (i & 15) * 4;
            float4 kv = *(const float4*)&qkv[(rowbase + k0 + r) * QKVCOLS + kcol + c4];
            unsigned* dk = &sK[r * 68 + c4];
            dk[0] = f2tf32(kv.x); dk[1] = f2tf32(kv.y);
            dk[2] = f2tf32(kv.z); dk[3] = f2tf32(kv.w);
            float4 vv = *(const float4*)&qkv[(rowbase + k0 + r) * QKVCOLS + vcol + c4];
            unsigned* dv = &sV[r * 72 + c4];
            dv[0] = f2tf32(vv.x); dv[1] = f2tf32(vv.y);
            dv[2] = f2tf32(vv.z); dv[3] = f2tf32(vv.w);
        }
        __syncthreads();

        // Per-warp causal early-out
        if (q0 + wr + 15 >= k0) {
            // ---- S = Q @ K^T : warp computes 16x64 ----
            float s[8][4];
#pragma unroll
            for (int nt = 0; nt < 8; nt++)
#pragma unroll
                for (int c = 0; c < 4; c++) s[nt][c] = 0.0f;
#pragma unroll
            for (int ks = 0; ks < 8; ks++) {
                const int k8 = ks * 8;
                unsigned bf[8][2];
#pragma unroll
                for (int ntp = 0; ntp < 4; ntp++)
                    LDMATRIX_X4(bf[2 * ntp][0], bf[2 * ntp][1],
                                bf[2 * ntp + 1][0], bf[2 * ntp + 1][1],
                                k_ldm + (ntp * 16 * 68 + k8) * 4);
#pragma unroll
                for (int nt = 0; nt < 8; nt++)
                    MMA_TF32(s[nt], qf[ks], bf[nt]);
            }

            // ---- Scale + causal mask ----
            const bool diag = (kt >= 2 * qt);
            const int rg0 = q0 + wr + g;
            const int rg1 = rg0 + 8;
#pragma unroll
            for (int nt = 0; nt < 8; nt++) {
                const int cg = k0 + nt * 8 + 2 * t4;
                s[nt][0] *= 0.125f; s[nt][1] *= 0.125f;
                s[nt][2] *= 0.125f; s[nt][3] *= 0.125f;
                if (diag) {
                    if (cg > rg0)     s[nt][0] = -1e9f;
                    if (cg + 1 > rg0) s[nt][1] = -1e9f;
                    if (cg > rg1)     s[nt][2] = -1e9f;
                    if (cg + 1 > rg1) s[nt][3] = -1e9f;
                }
            }

            // ---- Online softmax in registers (quad reduction) ----
            float mx0 = -1e30f, mx1 = -1e30f;
#pragma unroll
            for (int nt = 0; nt < 8; nt++) {
                mx0 = fmaxf(mx0, fmaxf(s[nt][0], s[nt][1]));
                mx1 = fmaxf(mx1, fmaxf(s[nt][2], s[nt][3]));
            }
            mx0 = fmaxf(mx0, __shfl_xor_sync(0xffffffffu, mx0, 1));
            mx0 = fmaxf(mx0, __shfl_xor_sync(0xffffffffu, mx0, 2));
            mx1 = fmaxf(mx1, __shfl_xor_sync(0xffffffffu, mx1, 1));
            mx1 = fmaxf(mx1, __shfl_xor_sync(0xffffffffu, mx1, 2));

            const float m0n = fmaxf(m0, mx0);
            const float m1n = fmaxf(m1, mx1);
            const float al0 = __expf(m0 - m0n);
            const float al1 = __expf(m1 - m1n);

            float sum0 = 0.0f, sum1 = 0.0f;
#pragma unroll
            for (int nt = 0; nt < 8; nt++) {
                s[nt][0] = __expf(s[nt][0] - m0n);
                s[nt][1] = __expf(s[nt][1] - m0n);
                s[nt][2] = __expf(s[nt][2] - m1n);
                s[nt][3] = __expf(s[nt][3] - m1n);
                sum0 += s[nt][0] + s[nt][1];
                sum1 += s[nt][2] + s[nt][3];
            }
            sum0 += __shfl_xor_sync(0xffffffffu, sum0, 1);
            sum0 += __shfl_xor_sync(0xffffffffu, sum0, 2);
            sum1 += __shfl_xor_sync(0xffffffffu, sum1, 1);
            sum1 += __shfl_xor_sync(0xffffffffu, sum1, 2);

            l0 = l0 * al0 + sum0;
            l1 = l1 * al1 + sum1;
            m0 = m0n; m1 = m1n;

#pragma unroll
            for (int nt = 0; nt < 8; nt++) {
                o[nt][0] *= al0; o[nt][1] *= al0;
                o[nt][2] *= al1; o[nt][3] *= al1;
            }

            // ---- Stage P (tf32) in warp-private sP rows ----
#pragma unroll
            for (int nt = 0; nt < 8; nt++) {
                const int c2 = nt * 8 + 2 * t4;
                sP[(wr + g) * 68 + c2]     = f2tf32(s[nt][0]);
                sP[(wr + g) * 68 + c2 + 1] = f2tf32(s[nt][1]);
                sP[(wr + g + 8) * 68 + c2]     = f2tf32(s[nt][2]);
                sP[(wr + g + 8) * 68 + c2 + 1] = f2tf32(s[nt][3]);
            }
            __syncwarp();

            // ---- O += P @ V ----
#pragma unroll
            for (int ks = 0; ks < 8; ks++) {
                const int k8 = ks * 8;
                unsigned a[4];
                LDMATRIX_X4(a[0], a[1], a[2], a[3], p_ldm + k8 * 4);
#pragma unroll
                for (int nt = 0; nt < 8; nt++) {
                    const int cc = nt * 8 + g;
                    unsigned bfr[2];
                    bfr[0] = sV[(k8 + t4) * 72 + cc];
                    bfr[1] = sV[(k8 + t4 + 4) * 72 + cc];
                    MMA_TF32(o[nt], a, bfr);
                }
            }
        }
        __syncthreads();   // protect sK/sV before next tile's loads
    }

    // ---- Normalize and store merged-head output ----
    const float inv0 = 1.0f / l0;
    const float inv1 = 1.0f / l1;
    const size_t r0 = rowbase + q0 + wr + g;
#pragma unroll
    for (int nt = 0; nt < 8; nt++) {
        const int col = h * HDIM + nt * 8 + 2 * t4;
        float2 v0, v1;
        v0.x = o[nt][0] * inv0; v0.y = o[nt][1] * inv0;
        v1.x = o[nt][2] * inv1; v1.y = o[nt][3] * inv1;
        *(float2*)&att[r0 * DMODEL + col] = v0;
        *(float2*)&att[(r0 + 8) * DMODEL + col] = v1;
    }
}

// ---------------------------------------------------------------------------
// Launch
// ---------------------------------------------------------------------------
extern "C" void kernel_launch(void* const* d_in, const int* in_sizes, int n_in,
                              void* d_out, int out_size)
{
    const float* x      = (const float*)d_in[0];  // [2,2048,1024]
    const float* W_qkv  = (const float*)d_in[1];  // [1024,3072]
    const float* b_qkv  = (const float*)d_in[2];  // [3072]
    const float* W_proj = (const float*)d_in[3];  // [1024,1024]
    const float* b_proj = (const float*)d_in[4];  // [1024]
    float* out          = (float*)d_out;          // [2,2048,1024]

    float* qkv_buf;  float* att_buf;
    unsigned* wqkvT; unsigned* wprojT;
    cudaGetSymbolAddress((void**)&qkv_buf, g_qkv);
    cudaGetSymbolAddress((void**)&att_buf, g_att);
    cudaGetSymbolAddress((void**)&wqkvT,  g_wqkvT);
    cudaGetSymbolAddress((void**)&wprojT, g_wprojT);

    cudaFuncSetAttribute(gemm_tf32_kernel,
                         cudaFuncAttributeMaxDynamicSharedMemorySize,
                         GEMM_SMEM_BYTES);
    cudaFuncSetAttribute(flash_attn_tf32_kernel,
                         cudaFuncAttributeMaxDynamicSharedMemorySize,
                         SMEM_ATT_BYTES);

    // 0) Pre-transpose weights to tf32 n-major
    {
        dim3 blk(32, 8);
        dim3 g1(QKVCOLS / 32, DMODEL / 32);
        transpose_tf32_kernel<<<g1, blk>>>(W_qkv, wqkvT, DMODEL, QKVCOLS);
        dim3 g2(DMODEL / 32, DMODEL / 32);
        transpose_tf32_kernel<<<g2, blk>>>(W_proj, wprojT, DMODEL, DMODEL);
    }

    // 1) QKV projection: [4096,1024] @ [1024,3072] + b
    {
        dim3 grid(QKVCOLS / 128, ROWS / 128);
        gemm_tf32_kernel<<<grid, 256, GEMM_SMEM_BYTES>>>(
            x, wqkvT, b_qkv, qkv_buf, ROWS, QKVCOLS, DMODEL);
    }

    // 2) Causal flash attention over all (batch, head, q-tile)
    {
        dim3 grid(SEQ / 128, BATCH * NHEADS);
        flash_attn_tf32_kernel<<<grid, 256, SMEM_ATT_BYTES>>>(qkv_buf, att_buf);
    }

    // 3) Output projection: [4096,1024] @ [1024,1024] + b
    {
        dim3 grid(DMODEL / 128, ROWS / 128);
        gemm_tf32_kernel<<<grid, 256, GEMM_SMEM_BYTES>>>(
            att_buf, wprojT, b_proj, out, ROWS, DMODEL, DMODEL);
    }
}

// round 7
// speedup vs baseline: 1.1889x; 1.1889x over previous
#include <cuda_runtime.h>
#include <math.h>

// Problem constants (fixed by the reference)
#define BATCH   2
#define SEQ     2048
#define DMODEL  1024
#define NHEADS  16
#define HDIM    64
#define ROWS    (BATCH * SEQ)        // 4096
#define QKVCOLS (3 * DMODEL)         // 3072

// Scratch (static device globals — allocation-free per harness rules)
__device__ float    g_qkv[(size_t)ROWS * QKVCOLS];      // 50 MB
__device__ float    g_att[(size_t)ROWS * DMODEL];       // 16 MB
__device__ unsigned g_wqkvT[(size_t)QKVCOLS * DMODEL];  // 12.6 MB (tf32 bits)
__device__ unsigned g_wprojT[(size_t)DMODEL * DMODEL];  // 4.2 MB  (tf32 bits)

// ---------------------------------------------------------------------------
// Helpers
// ---------------------------------------------------------------------------
__device__ __forceinline__ unsigned f2tf32(float x) {
    unsigned r;
    asm("cvt.rna.tf32.f32 %0, %1;" : "=r"(r) : "f"(x));
    return r;
}

// D += A(16x8) * B(8x8), tf32 inputs, fp32 accumulate
#define MMA_TF32(d, a, b)                                                     \
    asm volatile(                                                             \
        "mma.sync.aligned.m16n8k8.row.col.f32.tf32.tf32.f32 "                 \
        "{%0,%1,%2,%3},{%4,%5,%6,%7},{%8,%9},{%0,%1,%2,%3};"                  \
        : "+f"((d)[0]), "+f"((d)[1]), "+f"((d)[2]), "+f"((d)[3])              \
        : "r"((a)[0]), "r"((a)[1]), "r"((a)[2]), "r"((a)[3]),                 \
          "r"((b)[0]), "r"((b)[1]))

#define LDMATRIX_X4(r0, r1, r2, r3, addr)                                     \
    asm volatile(                                                             \
        "ldmatrix.sync.aligned.m8n8.x4.shared.b16 {%0,%1,%2,%3}, [%4];"       \
        : "=r"(r0), "=r"(r1), "=r"(r2), "=r"(r3) : "r"(addr))

__device__ __forceinline__ unsigned smem_u32(const void* p) {
    return (unsigned)__cvta_generic_to_shared(p);
}

// ---------------------------------------------------------------------------
// Weight pre-transpose: W[K][N] (f32) -> Wt[N][K] (tf32 bits)
// ---------------------------------------------------------------------------
__global__ void transpose_tf32_kernel(const float* __restrict__ W,
                                      unsigned* __restrict__ Wt,
                                      int K, int N)
{
    __shared__ unsigned t[32][33];
    const int x = blockIdx.x * 32 + threadIdx.x;   // n
    const int y = blockIdx.y * 32;                 // k base
#pragma unroll
    for (int j = threadIdx.y; j < 32; j += 8)
        t[j][threadIdx.x] = f2tf32(W[(size_t)(y + j) * N + x]);
    __syncthreads();
    const int xo = blockIdx.y * 32 + threadIdx.x;  // k
    const int yo = blockIdx.x * 32;                // n base
#pragma unroll
    for (int j = threadIdx.y; j < 32; j += 8)
        Wt[(size_t)(yo + j) * K + xo] = t[threadIdx.x][j];
}

// ---------------------------------------------------------------------------
// TF32 tensor-core GEMM: C[M,N] = A[M,K] @ W[K,N] + bias[N], with W given
// pre-transposed as Wt[N][K] in tf32 bits.
// Block 128x128, BK=32, 256 threads (8 warps, warp tile 32x64).
// Smem: As[2][128][36] (m-major tf32), Bs[2][128][36] (n-major tf32).
// All fragments via ldmatrix.x4 (conflict-free; 24 LDSM + 64 MMA /warp/tile).
// ---------------------------------------------------------------------------
#define GEMM_BUF   (128 * 36)
#define GEMM_SMEM_BYTES (4 * GEMM_BUF * 4)

__global__ __launch_bounds__(256, 2)
void gemm_tf32_kernel(const float* __restrict__ A,
                      const unsigned* __restrict__ Wt,
                      const float* __restrict__ bias,
                      float* __restrict__ C,
                      int M, int N, int K)
{
    extern __shared__ unsigned gsm[];
    unsigned* As = gsm;                  // [2][128][36]
    unsigned* Bs = gsm + 2 * GEMM_BUF;   // [2][128][36]

    const int tid  = threadIdx.x;
    const int lane = tid & 31;
    const int warp = tid >> 5;
    const int wm   = (warp >> 1) * 32;   // warp row offset in block tile
    const int wn   = (warp & 1) * 64;    // warp col offset
    const int row0 = blockIdx.y * 128;
    const int col0 = blockIdx.x * 128;

    float acc[2][8][4];
#pragma unroll
    for (int mt = 0; mt < 2; mt++)
#pragma unroll
        for (int nt = 0; nt < 8; nt++)
#pragma unroll
            for (int c = 0; c < 4; c++) acc[mt][nt][c] = 0.0f;

    // Loader coordinates: both tiles are 128 rows x 32 cols (float4/uint4)
    const int lr = tid >> 3;             // 0..31 (+32p)
    const int lc = (tid & 7) * 4;        // k-col
    const float*    Ap = A  + (size_t)(row0 + lr) * K + lc;
    const unsigned* Bp = Wt + (size_t)(col0 + lr) * K + lc;

    // ldmatrix per-lane base addresses
    const unsigned aRow = (lane & 15);
    const unsigned aCol = (lane >> 4) * 4;
    const unsigned a_ldm = smem_u32(As) + ((wm + aRow) * 36 + aCol) * 4;
    const unsigned bRow = (lane & 7) + ((lane & 16) >> 1);
    const unsigned bCol = (lane & 8) ? 4u : 0u;
    const unsigned b_ldm = smem_u32(Bs) + ((wn + bRow) * 36 + bCol) * 4;

    // Load first K-tile into buffer 0
    {
#pragma unroll
        for (int p = 0; p < 4; p++) {
            float4 av = *(const float4*)(Ap + (size_t)(p * 32) * K);
            uint4 u;
            u.x = f2tf32(av.x); u.y = f2tf32(av.y);
            u.z = f2tf32(av.z); u.w = f2tf32(av.w);
            *(uint4*)&As[(lr + p * 32) * 36 + lc] = u;
            *(uint4*)&Bs[(lr + p * 32) * 36 + lc] =
                *(const uint4*)(Bp + (size_t)(p * 32) * K);
        }
    }
    __syncthreads();

    int cur = 0;
    for (int k0 = 0; k0 < K; k0 += 32) {
        const int k1 = k0 + 32;
        float4 stA[4];
        uint4  stB[4];
        if (k1 < K) {
#pragma unroll
            for (int p = 0; p < 4; p++) {
                stA[p] = *(const float4*)(Ap + k1 + (size_t)(p * 32) * K);
                stB[p] = *(const uint4*)(Bp + k1 + (size_t)(p * 32) * K);
            }
        }

        const unsigned aBuf = a_ldm + cur * GEMM_BUF * 4;
        const unsigned bBuf = b_ldm + cur * GEMM_BUF * 4;
#pragma unroll
        for (int ks = 0; ks < 4; ks++) {
            const int k8 = ks * 8;
            unsigned af[2][4];
#pragma unroll
            for (int mt = 0; mt < 2; mt++)
                LDMATRIX_X4(af[mt][0], af[mt][1], af[mt][2], af[mt][3],
                            aBuf + (mt * 16 * 36 + k8) * 4);
            unsigned bf[8][2];
#pragma unroll
            for (int ntp = 0; ntp < 4; ntp++)
                LDMATRIX_X4(bf[2 * ntp][0], bf[2 * ntp][1],
                            bf[2 * ntp + 1][0], bf[2 * ntp + 1][1],
                            bBuf + (ntp * 16 * 36 + k8) * 4);
#pragma unroll
            for (int mt = 0; mt < 2; mt++)
#pragma unroll
                for (int nt = 0; nt < 8; nt++)
                    MMA_TF32(acc[mt][nt], af[mt], bf[nt]);
        }

        if (k1 < K) {
            unsigned* An = As + (cur ^ 1) * GEMM_BUF;
            unsigned* Bn = Bs + (cur ^ 1) * GEMM_BUF;
#pragma unroll
            for (int p = 0; p < 4; p++) {
                uint4 u;
                u.x = f2tf32(stA[p].x); u.y = f2tf32(stA[p].y);
                u.z = f2tf32(stA[p].z); u.w = f2tf32(stA[p].w);
                *(uint4*)&An[(lr + p * 32) * 36 + lc] = u;
                *(uint4*)&Bn[(lr + p * 32) * 36 + lc] = stB[p];
            }
        }
        __syncthreads();
        cur ^= 1;
    }

    // Epilogue: bias + float2 stores
    const int g  = lane >> 2;
    const int t4 = lane & 3;
#pragma unroll
    for (int mt = 0; mt < 2; mt++) {
        const int rA = row0 + wm + mt * 16 + g;
#pragma unroll
        for (int nt = 0; nt < 8; nt++) {
            const int c = col0 + wn + nt * 8 + 2 * t4;
            const float2 bv = *(const float2*)&bias[c];
            float2 o0, o1;
            o0.x = acc[mt][nt][0] + bv.x;
            o0.y = acc[mt][nt][1] + bv.y;
            o1.x = acc[mt][nt][2] + bv.x;
            o1.y = acc[mt][nt][3] + bv.y;
            *(float2*)&C[(size_t)rA * N + c] = o0;
            *(float2*)&C[(size_t)(rA + 8) * N + c] = o1;
        }
    }
}

// ---------------------------------------------------------------------------
// Flash attention v2-style: BQ=128 q-rows/block, BK=64 keys/tile, 8 warps.
// Warp w owns rows [16w,16w+16); softmax in registers; Q persistent in regs;
// ldmatrix for QK B-frags (sK n-major), Q and P A-frags (sP m-major).
//   sK[64][68] tf32, sV[64][72] tf32 (k-major, scalar b-frags), sP[128][68]
// __launch_bounds__(256,2): cap regs at 128 so 2 CTAs/SM fit (R6 ran at
// 135 regs -> 1 CTA/SM -> occ 12.5%, issue 23% -> regression).
// ---------------------------------------------------------------------------
#define SMEM_ATT_BYTES ((64 * 68 + 64 * 72 + 128 * 68) * 4)

__global__ __launch_bounds__(256, 2)
void flash_attn_tf32_kernel(const float* __restrict__ qkv,
                            float* __restrict__ att)
{
    extern __shared__ unsigned asm_[];
    unsigned* sK = asm_;                 // [64][68]
    unsigned* sV = sK + 64 * 68;         // [64][72]
    unsigned* sP = sV + 64 * 72;         // [128][68]  (Q staging, then P)

    const int tid  = threadIdx.x;
    const int lane = tid & 31;
    const int warp = tid >> 5;           // 0..7 -> rows [16w,16w+16)
    const int g    = lane >> 2;          // 0..7
    const int t4   = lane & 3;           // 0..3
    const int wr   = warp * 16;          // warp row base in q-tile

    const int bh = blockIdx.y;
    const int b  = bh / NHEADS;
    const int h  = bh % NHEADS;
    const int qt = gridDim.x - 1 - blockIdx.x;   // heavy tiles first
    const int q0 = qt * 128;

    const size_t rowbase = (size_t)b * SEQ;
    const int qcol = h * HDIM;
    const int kcol = DMODEL + h * HDIM;
    const int vcol = 2 * DMODEL + h * HDIM;

    // ldmatrix base addresses
    const unsigned kRow = (lane & 7) + ((lane & 16) >> 1);
    const unsigned kColOff = (lane & 8) ? 4u : 0u;
    const unsigned k_ldm = smem_u32(sK) + (kRow * 68 + kColOff) * 4;
    const unsigned pRow = wr + (lane & 15);
    const unsigned pColOff = (lane >> 4) * 4;
    const unsigned p_ldm = smem_u32(sP) + (pRow * 68 + pColOff) * 4;

    // ---- Stage Q tile (coalesced) into sP, convert tf32 ----
    for (int i = tid; i < 128 * 16; i += 256) {
        const int r  = i >> 4;
        const int c4 = (i & 15) * 4;
        float4 v = *(const float4*)&qkv[(rowbase + q0 + r) * QKVCOLS + qcol + c4];
        unsigned* d = &sP[r * 68 + c4];
        d[0] = f2tf32(v.x); d[1] = f2tf32(v.y);
        d[2] = f2tf32(v.z); d[3] = f2tf32(v.w);
    }
    __syncthreads();

    // Q a-frags via ldmatrix: qf[ks] covers k-cols [8ks,8ks+8)
    unsigned qf[8][4];
#pragma unroll
    for (int ks = 0; ks < 8; ks++)
        LDMATRIX_X4(qf[ks][0], qf[ks][1], qf[ks][2], qf[ks][3],
                    p_ldm + ks * 8 * 4);

    // Row stats (rows wr+g and wr+g+8) and output accum
    float m0 = -1e30f, m1 = -1e30f, l0 = 0.0f, l1 = 0.0f;
    float o[8][4];
#pragma unroll
    for (int nt = 0; nt < 8; nt++)
#pragma unroll
        for (int c = 0; c < 4; c++) o[nt][c] = 0.0f;

    const int n_kt = 2 * qt + 2;
    for (int kt = 0; kt < n_kt; kt++) {
        const int k0 = kt * 64;
        // ---- Load K, V tiles (tf32) ----
        for (int i = tid; i < 64 * 16; i += 256) {
            const int r  = i >> 4;
            const int c4 = (i & 15) * 4;
            float4 kv = *(const float4*)&qkv[(rowbase + k0 + r) * QKVCOLS + kcol + c4];
            unsigned* dk = &sK[r * 68 + c4];
            dk[0] = f2tf32(kv.x); dk[1] = f2tf32(kv.y);
            dk[2] = f2tf32(kv.z); dk[3] = f2tf32(kv.w);
            float4 vv = *(const float4*)&qkv[(rowbase + k0 + r) * QKVCOLS + vcol + c4];
            unsigned* dv = &sV[r * 72 + c4];
            dv[0] = f2tf32(vv.x); dv[1] = f2tf32(vv.y);
            dv[2] = f2tf32(vv.z); dv[3] = f2tf32(vv.w);
        }
        __syncthreads();

        // Per-warp causal early-out
        if (q0 + wr + 15 >= k0) {
            // ---- S = Q @ K^T : warp computes 16x64 ----
            float s[8][4];
#pragma unroll
            for (int nt = 0; nt < 8; nt++)
#pragma unroll
                for (int c = 0; c < 4; c++) s[nt][c] = 0.0f;
#pragma unroll
            for (int ks = 0; ks < 8; ks++) {
                const int k8 = ks * 8;
                unsigned bf[8][2];
#pragma unroll
                for (int ntp = 0; ntp < 4; ntp++)
                    LDMATRIX_X4(bf[2 * ntp][0], bf[2 * ntp][1],
                                bf[2 * ntp + 1][0], bf[2 * ntp + 1][1],
                                k_ldm + (ntp * 16 * 68 + k8) * 4);
#pragma unroll
                for (int nt = 0; nt < 8; nt++)
                    MMA_TF32(s[nt], qf[ks], bf[nt]);
            }

            // ---- Scale + causal mask ----
            const bool diag = (kt >= 2 * qt);
            const int rg0 = q0 + wr + g;
            const int rg1 = rg0 + 8;
#pragma unroll
            for (int nt = 0; nt < 8; nt++) {
                const int cg = k0 + nt * 8 + 2 * t4;
                s[nt][0] *= 0.125f; s[nt][1] *= 0.125f;
                s[nt][2] *= 0.125f; s[nt][3] *= 0.125f;
                if (diag) {
                    if (cg > rg0)     s[nt][0] = -1e9f;
                    if (cg + 1 > rg0) s[nt][1] = -1e9f;
                    if (cg > rg1)     s[nt][2] = -1e9f;
                    if (cg + 1 > rg1) s[nt][3] = -1e9f;
                }
            }

            // ---- Online softmax in registers (quad reduction) ----
            float mx0 = -1e30f, mx1 = -1e30f;
#pragma unroll
            for (int nt = 0; nt < 8; nt++) {
                mx0 = fmaxf(mx0, fmaxf(s[nt][0], s[nt][1]));
                mx1 = fmaxf(mx1, fmaxf(s[nt][2], s[nt][3]));
            }
            mx0 = fmaxf(mx0, __shfl_xor_sync(0xffffffffu, mx0, 1));
            mx0 = fmaxf(mx0, __shfl_xor_sync(0xffffffffu, mx0, 2));
            mx1 = fmaxf(mx1, __shfl_xor_sync(0xffffffffu, mx1, 1));
            mx1 = fmaxf(mx1, __shfl_xor_sync(0xffffffffu, mx1, 2));

            const float m0n = fmaxf(m0, mx0);
            const float m1n = fmaxf(m1, mx1);
            const float al0 = __expf(m0 - m0n);
            const float al1 = __expf(m1 - m1n);

            float sum0 = 0.0f, sum1 = 0.0f;
#pragma unroll
            for (int nt = 0; nt < 8; nt++) {
                s[nt][0] = __expf(s[nt][0] - m0n);
                s[nt][1] = __expf(s[nt][1] - m0n);
                s[nt][2] = __expf(s[nt][2] - m1n);
                s[nt][3] = __expf(s[nt][3] - m1n);
                sum0 += s[nt][0] + s[nt][1];
                sum1 += s[nt][2] + s[nt][3];
            }
            sum0 += __shfl_xor_sync(0xffffffffu, sum0, 1);
            sum0 += __shfl_xor_sync(0xffffffffu, sum0, 2);
            sum1 += __shfl_xor_sync(0xffffffffu, sum1, 1);
            sum1 += __shfl_xor_sync(0xffffffffu, sum1, 2);

            l0 = l0 * al0 + sum0;
            l1 = l1 * al1 + sum1;
            m0 = m0n; m1 = m1n;

#pragma unroll
            for (int nt = 0; nt < 8; nt++) {
                o[nt][0] *= al0; o[nt][1] *= al0;
                o[nt][2] *= al1; o[nt][3] *= al1;
            }

            // ---- Stage P (tf32) in warp-private sP rows ----
#pragma unroll
            for (int nt = 0; nt < 8; nt++) {
                const int c2 = nt * 8 + 2 * t4;
                sP[(wr + g) * 68 + c2]     = f2tf32(s[nt][0]);
                sP[(wr + g) * 68 + c2 + 1] = f2tf32(s[nt][1]);
                sP[(wr + g + 8) * 68 + c2]     = f2tf32(s[nt][2]);
                sP[(wr + g + 8) * 68 + c2 + 1] = f2tf32(s[nt][3]);
            }
            __syncwarp();

            // ---- O += P @ V ----
#pragma unroll
            for (int ks = 0; ks < 8; ks++) {
                const int k8 = ks * 8;
                unsigned a[4];
                LDMATRIX_X4(a[0], a[1], a[2], a[3], p_ldm + k8 * 4);
#pragma unroll
                for (int nt = 0; nt < 8; nt++) {
                    const int cc = nt * 8 + g;
                    unsigned bfr[2];
                    bfr[0] = sV[(k8 + t4) * 72 + cc];
                    bfr[1] = sV[(k8 + t4 + 4) * 72 + cc];
                    MMA_TF32(o[nt], a, bfr);
                }
            }
        }
        __syncthreads();   // protect sK/sV before next tile's loads
    }

    // ---- Normalize and store merged-head output ----
    const float inv0 = 1.0f / l0;
    const float inv1 = 1.0f / l1;
    const size_t r0 = rowbase + q0 + wr + g;
#pragma unroll
    for (int nt = 0; nt < 8; nt++) {
        const int col = h * HDIM + nt * 8 + 2 * t4;
        float2 v0, v1;
        v0.x = o[nt][0] * inv0; v0.y = o[nt][1] * inv0;
        v1.x = o[nt][2] * inv1; v1.y = o[nt][3] * inv1;
        *(float2*)&att[r0 * DMODEL + col] = v0;
        *(float2*)&att[(r0 + 8) * DMODEL + col] = v1;
    }
}

// ---------------------------------------------------------------------------
// Launch
// ---------------------------------------------------------------------------
extern "C" void kernel_launch(void* const* d_in, const int* in_sizes, int n_in,
                              void* d_out, int out_size)
{
    const float* x      = (const float*)d_in[0];  // [2,2048,1024]
    const float* W_qkv  = (const float*)d_in[1];  // [1024,3072]
    const float* b_qkv  = (const float*)d_in[2];  // [3072]
    const float* W_proj = (const float*)d_in[3];  // [1024,1024]
    const float* b_proj = (const float*)d_in[4];  // [1024]
    float* out          = (float*)d_out;          // [2,2048,1024]

    float* qkv_buf;  float* att_buf;
    unsigned* wqkvT; unsigned* wprojT;
    cudaGetSymbolAddress((void**)&qkv_buf, g_qkv);
    cudaGetSymbolAddress((void**)&att_buf, g_att);
    cudaGetSymbolAddress((void**)&wqkvT,  g_wqkvT);
    cudaGetSymbolAddress((void**)&wprojT, g_wprojT);

    cudaFuncSetAttribute(gemm_tf32_kernel,
                         cudaFuncAttributeMaxDynamicSharedMemorySize,
                         GEMM_SMEM_BYTES);
    cudaFuncSetAttribute(flash_attn_tf32_kernel,
                         cudaFuncAttributeMaxDynamicSharedMemorySize,
                         SMEM_ATT_BYTES);

    // 0) Pre-transpose weights to tf32 n-major
    {
        dim3 blk(32, 8);
        dim3 g1(QKVCOLS / 32, DMODEL / 32);
        transpose_tf32_kernel<<<g1, blk>>>(W_qkv, wqkvT, DMODEL, QKVCOLS);
        dim3 g2(DMODEL / 32, DMODEL / 32);
        transpose_tf32_kernel<<<g2, blk>>>(W_proj, wprojT, DMODEL, DMODEL);
    }

    // 1) QKV projection: [4096,1024] @ [1024,3072] + b
    {
        dim3 grid(QKVCOLS / 128, ROWS / 128);
        gemm_tf32_kernel<<<grid, 256, GEMM_SMEM_BYTES>>>(
            x, wqkvT, b_qkv, qkv_buf, ROWS, QKVCOLS, DMODEL);
    }

    // 2) Causal flash attention over all (batch, head, q-tile)
    {
        dim3 grid(SEQ / 128, BATCH * NHEADS);
        flash_attn_tf32_kernel<<<grid, 256, SMEM_ATT_BYTES>>>(qkv_buf, att_buf);
    }

    // 3) Output projection: [4096,1024] @ [1024,1024] + b
    {
        dim3 grid(DMODEL / 128, ROWS / 128);
        gemm_tf32_kernel<<<grid, 256, GEMM_SMEM_BYTES>>>(
            att_buf, wprojT, b_proj, out, ROWS, DMODEL, DMODEL);
    }
}

// round 8
// speedup vs baseline: 1.2747x; 1.0721x over previous
#include <cuda_runtime.h>
#include <math.h>

// Problem constants (fixed by the reference)
#define BATCH   2
#define SEQ     2048
#define DMODEL  1024
#define NHEADS  16
#define HDIM    64
#define ROWS    (BATCH * SEQ)        // 4096
#define QKVCOLS (3 * DMODEL)         // 3072

// Scratch (static device globals — allocation-free per harness rules)
__device__ unsigned g_qkv[(size_t)ROWS * QKVCOLS];      // 50 MB (tf32 bits)
__device__ float    g_att[(size_t)ROWS * DMODEL];       // 16 MB
__device__ unsigned g_wqkvT[(size_t)QKVCOLS * DMODEL];  // 12.6 MB (tf32 bits)
__device__ unsigned g_wprojT[(size_t)DMODEL * DMODEL];  // 4.2 MB  (tf32 bits)

// ---------------------------------------------------------------------------
// Helpers
// ---------------------------------------------------------------------------
__device__ __forceinline__ unsigned f2tf32(float x) {
    unsigned r;
    asm("cvt.rna.tf32.f32 %0, %1;" : "=r"(r) : "f"(x));
    return r;
}

// D += A(16x8) * B(8x8), tf32 inputs, fp32 accumulate
#define MMA_TF32(d, a, b)                                                     \
    asm volatile(                                                             \
        "mma.sync.aligned.m16n8k8.row.col.f32.tf32.tf32.f32 "                 \
        "{%0,%1,%2,%3},{%4,%5,%6,%7},{%8,%9},{%0,%1,%2,%3};"                  \
        : "+f"((d)[0]), "+f"((d)[1]), "+f"((d)[2]), "+f"((d)[3])              \
        : "r"((a)[0]), "r"((a)[1]), "r"((a)[2]), "r"((a)[3]),                 \
          "r"((b)[0]), "r"((b)[1]))

#define LDMATRIX_X4(r0, r1, r2, r3, addr)                                     \
    asm volatile(                                                             \
        "ldmatrix.sync.aligned.m8n8.x4.shared.b16 {%0,%1,%2,%3}, [%4];"       \
        : "=r"(r0), "=r"(r1), "=r"(r2), "=r"(r3) : "r"(addr))

__device__ __forceinline__ unsigned smem_u32(const void* p) {
    return (unsigned)__cvta_generic_to_shared(p);
}

__device__ __forceinline__ void cp_async16(unsigned dst, const void* src) {
    asm volatile("cp.async.cg.shared.global [%0], [%1], 16;"
                 :: "r"(dst), "l"(src));
}
#define CP_COMMIT() asm volatile("cp.async.commit_group;")
#define CP_WAIT(n)  asm volatile("cp.async.wait_group %0;" :: "n"(n))

// ---------------------------------------------------------------------------
// Weight pre-transpose: W[K][N] (f32) -> Wt[N][K] (tf32 bits)
// ---------------------------------------------------------------------------
__global__ void transpose_tf32_kernel(const float* __restrict__ W,
                                      unsigned* __restrict__ Wt,
                                      int K, int N)
{
    __shared__ unsigned t[32][33];
    const int x = blockIdx.x * 32 + threadIdx.x;   // n
    const int y = blockIdx.y * 32;                 // k base
#pragma unroll
    for (int j = threadIdx.y; j < 32; j += 8)
        t[j][threadIdx.x] = f2tf32(W[(size_t)(y + j) * N + x]);
    __syncthreads();
    const int xo = blockIdx.y * 32 + threadIdx.x;  // k
    const int yo = blockIdx.x * 32;                // n base
#pragma unroll
    for (int j = threadIdx.y; j < 32; j += 8)
        Wt[(size_t)(yo + j) * K + xo] = t[threadIdx.x][j];
}

// ---------------------------------------------------------------------------
// TF32 tensor-core GEMM: C[M,N] = A[M,K] @ W[K,N] + bias[N], Wt[N][K] tf32.
// OUT_TF32: epilogue stores tf32 bits (for the qkv buffer consumed by
// attention) instead of fp32 — numerically identical to converting there.
// ---------------------------------------------------------------------------
#define GEMM_BUF   (128 * 36)
#define GEMM_SMEM_BYTES (4 * GEMM_BUF * 4)

template <bool OUT_TF32>
__global__ __launch_bounds__(256, 2)
void gemm_tf32_kernel(const float* __restrict__ A,
                      const unsigned* __restrict__ Wt,
                      const float* __restrict__ bias,
                      void* __restrict__ Cv,
                      int M, int N, int K)
{
    extern __shared__ unsigned gsm[];
    unsigned* As = gsm;                  // [2][128][36]
    unsigned* Bs = gsm + 2 * GEMM_BUF;   // [2][128][36]

    const int tid  = threadIdx.x;
    const int lane = tid & 31;
    const int warp = tid >> 5;
    const int wm   = (warp >> 1) * 32;
    const int wn   = (warp & 1) * 64;
    const int row0 = blockIdx.y * 128;
    const int col0 = blockIdx.x * 128;

    float acc[2][8][4];
#pragma unroll
    for (int mt = 0; mt < 2; mt++)
#pragma unroll
        for (int nt = 0; nt < 8; nt++)
#pragma unroll
            for (int c = 0; c < 4; c++) acc[mt][nt][c] = 0.0f;

    const int lr = tid >> 3;
    const int lc = (tid & 7) * 4;
    const float*    Ap = A  + (size_t)(row0 + lr) * K + lc;
    const unsigned* Bp = Wt + (size_t)(col0 + lr) * K + lc;

    const unsigned aRow = (lane & 15);
    const unsigned aCol = (lane >> 4) * 4;
    const unsigned a_ldm = smem_u32(As) + ((wm + aRow) * 36 + aCol) * 4;
    const unsigned bRow = (lane & 7) + ((lane & 16) >> 1);
    const unsigned bCol = (lane & 8) ? 4u : 0u;
    const unsigned b_ldm = smem_u32(Bs) + ((wn + bRow) * 36 + bCol) * 4;

    {
#pragma unroll
        for (int p = 0; p < 4; p++) {
            float4 av = *(const float4*)(Ap + (size_t)(p * 32) * K);
            uint4 u;
            u.x = f2tf32(av.x); u.y = f2tf32(av.y);
            u.z = f2tf32(av.z); u.w = f2tf32(av.w);
            *(uint4*)&As[(lr + p * 32) * 36 + lc] = u;
            *(uint4*)&Bs[(lr + p * 32) * 36 + lc] =
                *(const uint4*)(Bp + (size_t)(p * 32) * K);
        }
    }
    __syncthreads();

    int cur = 0;
    for (int k0 = 0; k0 < K; k0 += 32) {
        const int k1 = k0 + 32;
        float4 stA[4];
        uint4  stB[4];
        if (k1 < K) {
#pragma unroll
            for (int p = 0; p < 4; p++) {
                stA[p] = *(const float4*)(Ap + k1 + (size_t)(p * 32) * K);
                stB[p] = *(const uint4*)(Bp + k1 + (size_t)(p * 32) * K);
            }
        }

        const unsigned aBuf = a_ldm + cur * GEMM_BUF * 4;
        const unsigned bBuf = b_ldm + cur * GEMM_BUF * 4;
#pragma unroll
        for (int ks = 0; ks < 4; ks++) {
            const int k8 = ks * 8;
            unsigned af[2][4];
#pragma unroll
            for (int mt = 0; mt < 2; mt++)
                LDMATRIX_X4(af[mt][0], af[mt][1], af[mt][2], af[mt][3],
                            aBuf + (mt * 16 * 36 + k8) * 4);
            unsigned bf[8][2];
#pragma unroll
            for (int ntp = 0; ntp < 4; ntp++)
                LDMATRIX_X4(bf[2 * ntp][0], bf[2 * ntp][1],
                            bf[2 * ntp + 1][0], bf[2 * ntp + 1][1],
                            bBuf + (ntp * 16 * 36 + k8) * 4);
#pragma unroll
            for (int mt = 0; mt < 2; mt++)
#pragma unroll
                for (int nt = 0; nt < 8; nt++)
                    MMA_TF32(acc[mt][nt], af[mt], bf[nt]);
        }

        if (k1 < K) {
            unsigned* An = As + (cur ^ 1) * GEMM_BUF;
            unsigned* Bn = Bs + (cur ^ 1) * GEMM_BUF;
#pragma unroll
            for (int p = 0; p < 4; p++) {
                uint4 u;
                u.x = f2tf32(stA[p].x); u.y = f2tf32(stA[p].y);
                u.z = f2tf32(stA[p].z); u.w = f2tf32(stA[p].w);
                *(uint4*)&An[(lr + p * 32) * 36 + lc] = u;
                *(uint4*)&Bn[(lr + p * 32) * 36 + lc] = stB[p];
            }
        }
        __syncthreads();
        cur ^= 1;
    }

    // Epilogue: bias + stores (fp32 or tf32 bits)
    const int g  = lane >> 2;
    const int t4 = lane & 3;
#pragma unroll
    for (int mt = 0; mt < 2; mt++) {
        const int rA = row0 + wm + mt * 16 + g;
#pragma unroll
        for (int nt = 0; nt < 8; nt++) {
            const int c = col0 + wn + nt * 8 + 2 * t4;
            const float2 bv = *(const float2*)&bias[c];
            if (OUT_TF32) {
                unsigned* C = (unsigned*)Cv;
                uint2 o0, o1;
                o0.x = f2tf32(acc[mt][nt][0] + bv.x);
                o0.y = f2tf32(acc[mt][nt][1] + bv.y);
                o1.x = f2tf32(acc[mt][nt][2] + bv.x);
                o1.y = f2tf32(acc[mt][nt][3] + bv.y);
                *(uint2*)&C[(size_t)rA * N + c] = o0;
                *(uint2*)&C[(size_t)(rA + 8) * N + c] = o1;
            } else {
                float* C = (float*)Cv;
                float2 o0, o1;
                o0.x = acc[mt][nt][0] + bv.x;
                o0.y = acc[mt][nt][1] + bv.y;
                o1.x = acc[mt][nt][2] + bv.x;
                o1.y = acc[mt][nt][3] + bv.y;
                *(float2*)&C[(size_t)rA * N + c] = o0;
                *(float2*)&C[(size_t)(rA + 8) * N + c] = o1;
            }
        }
    }
}

// ---------------------------------------------------------------------------
// Flash attention: BQ=128, BK=64, 8 warps; qkv already tf32 bits.
// cp.async double-buffered K/V: tile kt+1 loads overlap tile kt compute.
//   sK[2][64][68], sV[2][64][72], sP[128][68]  -> 104 KB, 2 CTAs/SM
// ---------------------------------------------------------------------------
#define SKT (64 * 68)
#define SVT (64 * 72)
#define SMEM_ATT_BYTES ((2 * SKT + 2 * SVT + 128 * 68) * 4)

__global__ __launch_bounds__(256, 2)
void flash_attn_tf32_kernel(const unsigned* __restrict__ qkv,
                            float* __restrict__ att)
{
    extern __shared__ unsigned asm_[];
    unsigned* sK = asm_;                 // [2][64][68]
    unsigned* sV = sK + 2 * SKT;         // [2][64][72]
    unsigned* sP = sV + 2 * SVT;         // [128][68]  (Q staging, then P)

    const int tid  = threadIdx.x;
    const int lane = tid & 31;
    const int warp = tid >> 5;           // 0..7 -> rows [16w,16w+16)
    const int g    = lane >> 2;
    const int t4   = lane & 3;
    const int wr   = warp * 16;

    const int bh = blockIdx.y;
    const int b  = bh / NHEADS;
    const int h  = bh % NHEADS;
    const int qt = gridDim.x - 1 - blockIdx.x;   // heavy tiles first
    const int q0 = qt * 128;

    const size_t rowbase = (size_t)b * SEQ;
    const int qcol = h * HDIM;
    const int kcol = DMODEL + h * HDIM;
    const int vcol = 2 * DMODEL + h * HDIM;

    // ldmatrix base addresses
    const unsigned kRow = (lane & 7) + ((lane & 16) >> 1);
    const unsigned kColOff = (lane & 8) ? 4u : 0u;
    const unsigned k_ldm = smem_u32(sK) + (kRow * 68 + kColOff) * 4;
    const unsigned pRow = wr + (lane & 15);
    const unsigned pColOff = (lane >> 4) * 4;
    const unsigned p_ldm = smem_u32(sP) + (pRow * 68 + pColOff) * 4;

    // Loader coords for K/V cp.async (16B per thread per pass)
    const int lvr = tid >> 4;            // 0..15 (+16 per pass)
    const int lvc = (tid & 15) * 4;      // 0..60
    const unsigned sKb = smem_u32(sK);
    const unsigned sVb = smem_u32(sV);

    // ---- Stage Q tile into sP (raw tf32 bits) ----
    for (int i = tid; i < 128 * 16; i += 256) {
        const int r  = i >> 4;
        const int c4 = (i & 15) * 4;
        *(uint4*)&sP[r * 68 + c4] =
            *(const uint4*)&qkv[(rowbase + q0 + r) * QKVCOLS + qcol + c4];
    }

    // ---- Prologue: async-load K/V tile 0 into buffer 0 ----
    {
#pragma unroll
        for (int p = 0; p < 4; p++) {
            const int r = lvr + p * 16;
            const size_t grow = (rowbase + r) * QKVCOLS;
            cp_async16(sKb + (r * 68 + lvc) * 4, &qkv[grow + kcol + lvc]);
            cp_async16(sVb + (r * 72 + lvc) * 4, &qkv[grow + vcol + lvc]);
        }
        CP_COMMIT();
    }
    __syncthreads();   // sP (Q) visible to all warps

    // Q a-frags via ldmatrix
    unsigned qf[8][4];
#pragma unroll
    for (int ks = 0; ks < 8; ks++)
        LDMATRIX_X4(qf[ks][0], qf[ks][1], qf[ks][2], qf[ks][3],
                    p_ldm + ks * 8 * 4);

    float m0 = -1e30f, m1 = -1e30f, l0 = 0.0f, l1 = 0.0f;
    float o[8][4];
#pragma unroll
    for (int nt = 0; nt < 8; nt++)
#pragma unroll
        for (int c = 0; c < 4; c++) o[nt][c] = 0.0f;

    const int n_kt = 2 * qt + 2;
    for (int kt = 0; kt < n_kt; kt++) {
        const int buf = kt & 1;

        // Issue next tile's loads into the other buffer (overlaps compute wait)
        if (kt + 1 < n_kt) {
            const int k0n = (kt + 1) * 64;
            const unsigned sKn = sKb + (buf ^ 1) * SKT * 4;
            const unsigned sVn = sVb + (buf ^ 1) * SVT * 4;
#pragma unroll
            for (int p = 0; p < 4; p++) {
                const int r = lvr + p * 16;
                const size_t grow = (rowbase + k0n + r) * QKVCOLS;
                cp_async16(sKn + (r * 68 + lvc) * 4, &qkv[grow + kcol + lvc]);
                cp_async16(sVn + (r * 72 + lvc) * 4, &qkv[grow + vcol + lvc]);
            }
            CP_COMMIT();
            CP_WAIT(1);    // tile kt's group complete
        } else {
            CP_WAIT(0);
        }
        __syncthreads();

        // Per-warp causal early-out
        const int k0 = kt * 64;
        if (q0 + wr + 15 >= k0) {
            const unsigned kb = k_ldm + buf * SKT * 4;
            const unsigned* sVc = sV + buf * SVT;

            // ---- S = Q @ K^T ----
            float s[8][4];
#pragma unroll
            for (int nt = 0; nt < 8; nt++)
#pragma unroll
                for (int c = 0; c < 4; c++) s[nt][c] = 0.0f;
#pragma unroll
            for (int ks = 0; ks < 8; ks++) {
                const int k8 = ks * 8;
                unsigned bf[8][2];
#pragma unroll
                for (int ntp = 0; ntp < 4; ntp++)
                    LDMATRIX_X4(bf[2 * ntp][0], bf[2 * ntp][1],
                                bf[2 * ntp + 1][0], bf[2 * ntp + 1][1],
                                kb + (ntp * 16 * 68 + k8) * 4);
#pragma unroll
                for (int nt = 0; nt < 8; nt++)
                    MMA_TF32(s[nt], qf[ks], bf[nt]);
            }

            // ---- Scale + causal mask ----
            const bool diag = (kt >= 2 * qt);
            const int rg0 = q0 + wr + g;
            const int rg1 = rg0 + 8;
#pragma unroll
            for (int nt = 0; nt < 8; nt++) {
                const int cg = k0 + nt * 8 + 2 * t4;
                s[nt][0] *= 0.125f; s[nt][1] *= 0.125f;
                s[nt][2] *= 0.125f; s[nt][3] *= 0.125f;
                if (diag) {
                    if (cg > rg0)     s[nt][0] = -1e9f;
                    if (cg + 1 > rg0) s[nt][1] = -1e9f;
                    if (cg > rg1)     s[nt][2] = -1e9f;
                    if (cg + 1 > rg1) s[nt][3] = -1e9f;
                }
            }

            // ---- Online softmax in registers ----
            float mx0 = -1e30f, mx1 = -1e30f;
#pragma unroll
            for (int nt = 0; nt < 8; nt++) {
                mx0 = fmaxf(mx0, fmaxf(s[nt][0], s[nt][1]));
                mx1 = fmaxf(mx1, fmaxf(s[nt][2], s[nt][3]));
            }
            mx0 = fmaxf(mx0, __shfl_xor_sync(0xffffffffu, mx0, 1));
            mx0 = fmaxf(mx0, __shfl_xor_sync(0xffffffffu, mx0, 2));
            mx1 = fmaxf(mx1, __shfl_xor_sync(0xffffffffu, mx1, 1));
            mx1 = fmaxf(mx1, __shfl_xor_sync(0xffffffffu, mx1, 2));

            const float m0n = fmaxf(m0, mx0);
            const float m1n = fmaxf(m1, mx1);
            const float al0 = __expf(m0 - m0n);
            const float al1 = __expf(m1 - m1n);

            float sum0 = 0.0f, sum1 = 0.0f;
#pragma unroll
            for (int nt = 0; nt < 8; nt++) {
                s[nt][0] = __expf(s[nt][0] - m0n);
                s[nt][1] = __expf(s[nt][1] - m0n);
                s[nt][2] = __expf(s[nt][2] - m1n);
                s[nt][3] = __expf(s[nt][3] - m1n);
                sum0 += s[nt][0] + s[nt][1];
                sum1 += s[nt][2] + s[nt][3];
            }
            sum0 += __shfl_xor_sync(0xffffffffu, sum0, 1);
            sum0 += __shfl_xor_sync(0xffffffffu, sum0, 2);
            sum1 += __shfl_xor_sync(0xffffffffu, sum1, 1);
            sum1 += __shfl_xor_sync(0xffffffffu, sum1, 2);

            l0 = l0 * al0 + sum0;
            l1 = l1 * al1 + sum1;
            m0 = m0n; m1 = m1n;

#pragma unroll
            for (int nt = 0; nt < 8; nt++) {
                o[nt][0] *= al0; o[nt][1] *= al0;
                o[nt][2] *= al1; o[nt][3] *= al1;
            }

            // ---- Stage P (tf32) in warp-private sP rows ----
#pragma unroll
            for (int nt = 0; nt < 8; nt++) {
                const int c2 = nt * 8 + 2 * t4;
                sP[(wr + g) * 68 + c2]     = f2tf32(s[nt][0]);
                sP[(wr + g) * 68 + c2 + 1] = f2tf32(s[nt][1]);
                sP[(wr + g + 8) * 68 + c2]     = f2tf32(s[nt][2]);
                sP[(wr + g + 8) * 68 + c2 + 1] = f2tf32(s[nt][3]);
            }
            __syncwarp();

            // ---- O += P @ V ----
#pragma unroll
            for (int ks = 0; ks < 8; ks++) {
                const int k8 = ks * 8;
                unsigned a[4];
                LDMATRIX_X4(a[0], a[1], a[2], a[3], p_ldm + k8 * 4);
#pragma unroll
                for (int nt = 0; nt < 8; nt++) {
                    const int cc = nt * 8 + g;
                    unsigned bfr[2];
                    bfr[0] = sVc[(k8 + t4) * 72 + cc];
                    bfr[1] = sVc[(k8 + t4 + 4) * 72 + cc];
                    MMA_TF32(o[nt], a, bfr);
                }
            }
        }
        __syncthreads();   // all done with buf before next-next issue reuses it
    }

    // ---- Normalize and store merged-head output ----
    const float inv0 = 1.0f / l0;
    const float inv1 = 1.0f / l1;
    const size_t r0 = rowbase + q0 + wr + g;
#pragma unroll
    for (int nt = 0; nt < 8; nt++) {
        const int col = h * HDIM + nt * 8 + 2 * t4;
        float2 v0, v1;
        v0.x = o[nt][0] * inv0; v0.y = o[nt][1] * inv0;
        v1.x = o[nt][2] * inv1; v1.y = o[nt][3] * inv1;
        *(float2*)&att[r0 * DMODEL + col] = v0;
        *(float2*)&att[(r0 + 8) * DMODEL + col] = v1;
    }
}

// ---------------------------------------------------------------------------
// Launch
// ---------------------------------------------------------------------------
extern "C" void kernel_launch(void* const* d_in, const int* in_sizes, int n_in,
                              void* d_out, int out_size)
{
    const float* x      = (const float*)d_in[0];  // [2,2048,1024]
    const float* W_qkv  = (const float*)d_in[1];  // [1024,3072]
    const float* b_qkv  = (const float*)d_in[2];  // [3072]
    const float* W_proj = (const float*)d_in[3];  // [1024,1024]
    const float* b_proj = (const float*)d_in[4];  // [1024]
    float* out          = (float*)d_out;          // [2,2048,1024]

    unsigned* qkv_buf; float* att_buf;
    unsigned* wqkvT;   unsigned* wprojT;
    cudaGetSymbolAddress((void**)&qkv_buf, g_qkv);
    cudaGetSymbolAddress((void**)&att_buf, g_att);
    cudaGetSymbolAddress((void**)&wqkvT,  g_wqkvT);
    cudaGetSymbolAddress((void**)&wprojT, g_wprojT);

    cudaFuncSetAttribute(gemm_tf32_kernel<true>,
                         cudaFuncAttributeMaxDynamicSharedMemorySize,
                         GEMM_SMEM_BYTES);
    cudaFuncSetAttribute(gemm_tf32_kernel<false>,
                         cudaFuncAttributeMaxDynamicSharedMemorySize,
                         GEMM_SMEM_BYTES);
    cudaFuncSetAttribute(flash_attn_tf32_kernel,
                         cudaFuncAttributeMaxDynamicSharedMemorySize,
                         SMEM_ATT_BYTES);

    // 0) Pre-transpose weights to tf32 n-major
    {
        dim3 blk(32, 8);
        dim3 g1(QKVCOLS / 32, DMODEL / 32);
        transpose_tf32_kernel<<<g1, blk>>>(W_qkv, wqkvT, DMODEL, QKVCOLS);
        dim3 g2(DMODEL / 32, DMODEL / 32);
        transpose_tf32_kernel<<<g2, blk>>>(W_proj, wprojT, DMODEL, DMODEL);
    }

    // 1) QKV projection -> tf32-bit qkv buffer
    {
        dim3 grid(QKVCOLS / 128, ROWS / 128);
        gemm_tf32_kernel<true><<<grid, 256, GEMM_SMEM_BYTES>>>(
            x, wqkvT, b_qkv, qkv_buf, ROWS, QKVCOLS, DMODEL);
    }

    // 2) Causal flash attention
    {
        dim3 grid(SEQ / 128, BATCH * NHEADS);
        flash_attn_tf32_kernel<<<grid, 256, SMEM_ATT_BYTES>>>(qkv_buf, att_buf);
    }

    // 3) Output projection -> fp32 out
    {
        dim3 grid(DMODEL / 128, ROWS / 128);
        gemm_tf32_kernel<false><<<grid, 256, GEMM_SMEM_BYTES>>>(
            att_buf, wprojT, b_proj, out, ROWS, DMODEL, DMODEL);
    }
}